// round 17
// baseline (speedup 1.0000x reference)
#include <cuda_runtime.h>
#include <cuda_fp16.h>
#include <cstdint>

#define N_IN     256
#define DDEG     8
#define N_OUT    64
#define M_TILE   256
#define N_CHUNKS 32

// Two private groups per CTA; per group: A double-buffered 16KB, B 8KB.
#define GRP_BYTES 49152
#define GA(g, p)  ((g) * GRP_BYTES + (p) * 16384)
#define GB(g, p)  ((g) * GRP_BYTES + 32768 + (p) * 8192)
#define SM_TOTAL  (2 * GRP_BYTES)          // 98304

// A-tile in-block swizzle: slot for (fr, c) within a (ks, mtile) 512B block.
// Conflict-free for gen STS.64 phases and consumer LDS.128 phases (round-8 proof;
// block bases are multiples of 512B so bank patterns are block-invariant).
#define ASWZ3(fr, c, ks) ((((fr) + 2 * (c) + 4 * (((ks) >> 1) & 1)) & 7) + 8 * (c))

// B prepacked as exact per-chunk smem fragment images: 32 chunks x 4096 halves
__device__ __half g_Bpack[N_CHUNKS * 4096];

__global__ void repack_kernel(const float* __restrict__ c_basis) {
    int idx = blockIdx.x * 256 + threadIdx.x;          // 131072 total
    int e    = idx & 7;
    int lane = (idx >> 3) & 31;
    int ng   = (idx >> 8) & 3;
    int ks   = (idx >> 10) & 3;
    int ch   = idx >> 12;
    int nt = ng * 2 + (e >> 2);
    int bp = (e >> 1) & 1;                             // b01 vs b23 (k +8)
    int h  = e & 1;
    int k  = ks * 16 + bp * 8 + (lane & 3) * 2 + h;    // k within chunk
    int n  = nt * 8 + (lane >> 2);
    int kg = ch * 64 + k;
    int i = kg >> 3, d = kg & 7;
    g_Bpack[idx] = __float2half_rn(c_basis[(n * N_IN + i) * DDEG + d]);
}

#define MMA16816(ac, A0, A1, A2, A3, B0, B1)                                  \
    asm volatile(                                                             \
        "mma.sync.aligned.m16n8k16.row.col.f32.f16.f16.f32 "                  \
        "{%0,%1,%2,%3}, {%4,%5,%6,%7}, {%8,%9}, {%0,%1,%2,%3};"               \
        : "+f"((ac)[0]), "+f"((ac)[1]), "+f"((ac)[2]), "+f"((ac)[3])          \
        : "r"(A0), "r"(A1), "r"(A2), "r"(A3), "r"(B0), "r"(B1))

__device__ __forceinline__ void cp_async16(uint32_t saddr, const void* gptr) {
    asm volatile("cp.async.ca.shared.global [%0], [%1], 16;"
                 :: "r"(saddr), "l"(gptr) : "memory");
}

__device__ __forceinline__ void group_bar(int g) {
    asm volatile("bar.sync %0, %1;" :: "r"(1 + g), "r"(128) : "memory");
}

// Generate one (row, 4 feats) quartet into A-slots: 8 STS.64, conflict-free.
// Group A-tile blocking: (ks*8 + mt)*512, mt 0..7 (128 rows per group).
__device__ __forceinline__ void gen_tile(char* Ab, float4 xv,
                                         int mt_g, int fr_g, int half, int sh_g) {
    float xf[4] = {xv.x, xv.y, xv.z, xv.w};
    uint32_t hp[4][4];                         // [feat][c-pair] half2 bits
    #pragma unroll
    for (int f = 0; f < 4; f++) {
        float e2 = __expf(2.0f * xf[f]);
        float t  = 1.0f - __fdividef(2.0f, e2 + 1.0f);
        float pv[8];
        pv[0] = t;
        float pp = 1.0f, pc = t;
        #pragma unroll
        for (int d = 1; d < 8; d++) {
            float kk = (float)(d + 1);
            float a_ = (2.0f * kk - 1.0f) / kk;
            float b_ = (kk - 1.0f) / kk;
            float pn = a_ * t * pc - b_ * pp;
            pv[d] = pn; pp = pc; pc = pn;
        }
        #pragma unroll
        for (int cc = 0; cc < 4; cc++) {
            __half2 h2 = __floats2half2_rn(pv[2 * cc], pv[2 * cc + 1]);
            hp[f][cc] = *(uint32_t*)&h2;
        }
    }
    #pragma unroll
    for (int p2 = 0; p2 < 2; p2++) {
        int ks = half * 2 + p2;
        char* blk = Ab + (ks * 8 + mt_g) * 512 + sh_g;
        #pragma unroll
        for (int cc = 0; cc < 4; cc++) {
            uint2 v = make_uint2(hp[p2 * 2][cc], hp[p2 * 2 + 1][cc]);
            *(uint2*)(blk + ASWZ3(fr_g, cc, ks) * 16) = v;
        }
    }
}

extern __shared__ __align__(128) char sm[];

__global__ __launch_bounds__(256, 2)
void kan_fp16_kernel(const float* __restrict__ x, const float* __restrict__ bias,
                     float* __restrict__ y, int batch) {
    const int tid  = threadIdx.x;
    const int lane = tid & 31;
    const int wid  = tid >> 5;
    const int g    = tid >> 7;         // group 0: warps 0-3, group 1: warps 4-7
    const int gtid = tid & 127;
    const int w_in = wid & 3;          // warp within group: m32 rows, all 64 cols
    const int rowBase = blockIdx.x * M_TILE + g * 128;
    const uint32_t sbase = (uint32_t)__cvta_generic_to_shared(sm);

    // ---- gen mapping (within group): adjacent lanes = two feat-halves of the
    // SAME row; each thread covers rows {grow, grow+64} (two passes) ----
    const int grow = gtid >> 1;                  // 0..63
    const int half = gtid & 1;                   // feats half*4 .. half*4+3
    const int mt_g = grow >> 4;                  // m-tile 0..3 (pass 0); +4 pass 1
    const int rh_g = (grow >> 3) & 1;
    const int fr_g = grow & 7;
    int rg0 = rowBase + grow;       if (rg0 > batch - 1) rg0 = batch - 1;
    int rg1 = rowBase + grow + 64;  if (rg1 > batch - 1) rg1 = batch - 1;
    const float* xrow0 = x + (size_t)rg0 * N_IN + half * 4;
    const float* xrow1 = x + (size_t)rg1 * N_IN + half * 4;
    const int sh_g = (rh_g ^ half) * 8;

    // ---- consumer fragment indices ----
    const int c  = lane & 3;
    const int fr = lane >> 2;
    const uint32_t aoffL = (uint32_t)(w_in * 1024 + ASWZ3(fr, c, 0) * 16);
    const uint32_t aoffH = (uint32_t)(w_in * 1024 + ASWZ3(fr, c, 2) * 16);
    const uint32_t boff  = (uint32_t)(lane * 16);

    float acc[2][8][4] = {};

    // ---- prolog: stage B(0) for this group (4 x cp.async16 per thread) ----
    {
        const char* src = (const char*)g_Bpack;
        #pragma unroll
        for (int q = 0; q < 4; q++)
            cp_async16(sbase + GB(g, 0) + q * 2048 + gtid * 16,
                       src + q * 2048 + gtid * 16);
        asm volatile("cp.async.commit_group;" ::: "memory");
    }
    float4 xv0 = *(const float4*)xrow0;
    float4 xv1 = *(const float4*)xrow1;

    for (int ch = 0; ch < N_CHUNKS; ch++) {
        const int p = ch & 1;

        // ---- generate A(ch): two row-passes into the group's A buffer ----
        {
            char* Ab = sm + GA(g, p);
            float4 xa = xv0, xb = xv1;
            if (ch + 1 < N_CHUNKS) {
                xv0 = *(const float4*)(xrow0 + (ch + 1) * 8);
                xv1 = *(const float4*)(xrow1 + (ch + 1) * 8);
            }
            gen_tile(Ab, xa, mt_g,     fr_g, half, sh_g);
            gen_tile(Ab, xb, mt_g + 4, fr_g, half, sh_g);
        }

        // ---- B(ch) arrived + A(ch) visible (group-scope barrier) ----
        asm volatile("cp.async.wait_group 0;" ::: "memory");
        group_bar(g);

        // ---- prefetch B(ch+1) (safe: group finished MMA(ch-1)) ----
        if (ch + 1 < N_CHUNKS) {
            const char* src = (const char*)g_Bpack + (size_t)(ch + 1) * 8192;
            #pragma unroll
            for (int q = 0; q < 4; q++)
                cp_async16(sbase + GB(g, p ^ 1) + q * 2048 + gtid * 16,
                           src + q * 2048 + gtid * 16);
            asm volatile("cp.async.commit_group;" ::: "memory");
        }

        // ---- MMA(ch): 4 k-steps x (2 m-tiles x 8 n-tiles) m16n8k16 ----
        // ks<2: slot = (rl.i0, rl.i1, rh.i0, rh.i1) -> A order (x,z,y,w)
        // ks>=2: byte-halves swapped -> A order (z,x,w,y)
        {
            const char* Ar = sm + GA(g, p);
            const char* Br = sm + GB(g, p);
            #pragma unroll
            for (int ks = 0; ks < 4; ks++) {
                uint4 a0 = *(const uint4*)(Ar + ks * 4096 + aoffL * (ks < 2) + aoffH * (ks >= 2));
                uint4 a1 = *(const uint4*)(Ar + ks * 4096 + 512 + aoffL * (ks < 2) + aoffH * (ks >= 2));
                uint4 bq[4];
                #pragma unroll
                for (int q = 0; q < 4; q++)
                    bq[q] = *(const uint4*)(Br + (ks * 4 + q) * 512 + boff);
                const uint32_t* bp = (const uint32_t*)bq;
                if (ks < 2) {
                    #pragma unroll
                    for (int nt = 0; nt < 8; nt++) {
                        MMA16816(acc[0][nt], a0.x, a0.z, a0.y, a0.w, bp[2 * nt], bp[2 * nt + 1]);
                        MMA16816(acc[1][nt], a1.x, a1.z, a1.y, a1.w, bp[2 * nt], bp[2 * nt + 1]);
                    }
                } else {
                    #pragma unroll
                    for (int nt = 0; nt < 8; nt++) {
                        MMA16816(acc[0][nt], a0.z, a0.x, a0.w, a0.y, bp[2 * nt], bp[2 * nt + 1]);
                        MMA16816(acc[1][nt], a1.z, a1.x, a1.w, a1.y, bp[2 * nt], bp[2 * nt + 1]);
                    }
                }
            }
        }
    }

    // ---- epilogue: bias + store (warp covers its m32 rows, all 64 cols) ----
    #pragma unroll
    for (int t = 0; t < 2; t++) {
        int r0 = rowBase + w_in * 32 + t * 16 + fr;
        #pragma unroll
        for (int nt = 0; nt < 8; nt++) {
            int col = nt * 8 + c * 2;
            float2 bb = *(const float2*)(bias + col);
            if (r0 < batch)
                *(float2*)(y + (size_t)r0 * N_OUT + col) =
                    make_float2(acc[t][nt][0] + bb.x, acc[t][nt][1] + bb.y);
            if (r0 + 8 < batch)
                *(float2*)(y + (size_t)(r0 + 8) * N_OUT + col) =
                    make_float2(acc[t][nt][2] + bb.x, acc[t][nt][3] + bb.y);
        }
    }
}

extern "C" void kernel_launch(void* const* d_in, const int* in_sizes, int n_in,
                              void* d_out, int out_size) {
    const float* x       = (const float*)d_in[0];
    const float* c_basis = (const float*)d_in[1];
    const float* bias    = (const float*)d_in[2];
    float* y = (float*)d_out;
    int batch = in_sizes[0] / N_IN;

    cudaFuncSetAttribute(kan_fp16_kernel,
                         cudaFuncAttributeMaxDynamicSharedMemorySize, SM_TOTAL);

    repack_kernel<<<(N_CHUNKS * 4096) / 256, 256>>>(c_basis);
    int grid = (batch + M_TILE - 1) / M_TILE;
    kan_fp16_kernel<<<grid, 256, SM_TOTAL>>>(x, bias, y, batch);
}